// round 3
// baseline (speedup 1.0000x reference)
#include <cuda_runtime.h>
#include <math.h>
#include <float.h>

#define BB 8
#define NN 4096
#define KK 9
#define ROWS (BB*NN*KK)   /* 294912 */
#define QPB 128           /* queries per block (knn kernel) */
#define SLICES 2
#define SLICE_LEN (NN/SLICES)
#define NB1 (NN/QPB*BB)   /* 256 knn blocks */
#define NB3 512

// Scratch (allocation-free: __device__ globals)
__device__ float g_h1[ROWS*10];
__device__ float g_h2[ROWS*10];
__device__ float g_p1[NB1*20];
__device__ float g_p2[NB3*20];
__device__ float g_s1[20];   // mu[10], inv[10]
__device__ float g_s2[20];

__device__ __forceinline__ bool dless(float d1, int j1, float d2, int j2) {
    return d1 < d2 || (d1 == d2 && j1 < j2);
}

// ---------------------------------------------------------------------------
// Kernel 1: kNN top-10 (2 threads/query, chunked ILP) + features + linear1
//           + BN1 partial stats
// grid (NN/QPB, BB), block 256
// ---------------------------------------------------------------------------
__global__ __launch_bounds__(256) void knn_feat_kernel(const float* __restrict__ x,
                                                       const float* __restrict__ W1,
                                                       const float* __restrict__ b1) {
    extern __shared__ float4 sx[];                 // [NN]  64KB
    float* sW  = (float*)&sx[NN];                  // 100
    float* sb  = sW + 100;                         // 10
    float* smd = sb + 10;                          // QPB*SLICES*10 floats (per query: 20 contiguous)
    int*   smi = (int*)(smd + QPB*SLICES*10);      // same count ints

    const int tid = threadIdx.x;
    const int b = blockIdx.y;
    const float* xb = x + (size_t)b * NN * 3;

    for (int j = tid; j < NN; j += blockDim.x) {
        float xx = xb[j*3+0], yy = xb[j*3+1], zz = xb[j*3+2];
        float w = fmaf(zz, zz, fmaf(yy, yy, xx*xx));
        sx[j] = make_float4(xx, yy, zz, w);
    }
    if (tid < 100) sW[tid] = W1[tid];
    if (tid < 10)  sb[tid] = b1[tid];
    __syncthreads();

    // ---------------- Phase B: kNN over one slice ----------------
    {
        const int q = tid >> 1;          // 0..127
        const int s = tid & 1;           // slice
        const int n = blockIdx.x * QPB + q;
        const float4 qv = sx[n];
        const float qx = qv.x, qy = qv.y, qz = qv.z, q2 = qv.w;

        float bd[10]; int bi[10];
        #pragma unroll
        for (int t = 0; t < 10; ++t) { bd[t] = FLT_MAX; bi[t] = 0x7fffffff; }

        const int jbeg = s * SLICE_LEN, jend = jbeg + SLICE_LEN;
        for (int j0 = jbeg; j0 < jend; j0 += 8) {
            float dd[8];
            #pragma unroll
            for (int u = 0; u < 8; ++u) {
                float4 c = sx[j0 + u];
                float dot = fmaf(qz, c.z, fmaf(qy, c.y, qx * c.x));
                // match reference: (x2n + x2m) - 2*dot, no fma contraction on combine
                dd[u] = __fsub_rn(__fadd_rn(q2, c.w), __fmul_rn(2.0f, dot));
            }
            float dmin = dd[0];
            #pragma unroll
            for (int u = 1; u < 8; ++u) dmin = fminf(dmin, dd[u]);
            if (dmin <= bd[9]) {
                #pragma unroll
                for (int u = 0; u < 8; ++u) {
                    const int j = j0 + u;
                    if (dless(dd[u], j, bd[9], bi[9])) {
                        float cd = dd[u]; int cj = j;
                        #pragma unroll
                        for (int t = 0; t < 10; ++t) {
                            if (dless(cd, cj, bd[t], bi[t])) {
                                float td = bd[t]; bd[t] = cd; cd = td;
                                int ti = bi[t]; bi[t] = cj; cj = ti;
                            }
                        }
                    }
                }
            }
        }
        // write this slice's sorted list
        float* md = smd + q*20 + s*10;
        int*   mi = smi + q*20 + s*10;
        #pragma unroll
        for (int t = 0; t < 10; ++t) { md[t] = bd[t]; mi[t] = bi[t]; }
    }
    __syncthreads();

    // ---------------- Phase C: merge + features + linear1 ----------------
    float ls[10], ls2[10];
    #pragma unroll
    for (int o = 0; o < 10; ++o) { ls[o] = 0.0f; ls2[o] = 0.0f; }

    if (tid < QPB) {
        const int q = tid;
        const int n = blockIdx.x * QPB + q;
        const float4 qv = sx[n];
        const float qx = qv.x, qy = qv.y, qz = qv.z;

        // 2-way merge of sorted (d,i) lists; slice0 indices < slice1 indices
        const float* md = smd + q*20;
        const int*   mi = smi + q*20;
        int midx[10];
        {
            int p0 = 0, p1 = 0;
            #pragma unroll
            for (int t = 0; t < 10; ++t) {
                float d0 = md[p0], d1 = md[10 + p1];
                int   i0 = mi[p0], i1 = mi[10 + p1];
                bool take0 = (p1 >= 10) || (p0 < 10 && dless(d0, i0, d1, i1));
                midx[t] = take0 ? i0 : i1;
                if (take0) ++p0; else ++p1;
            }
        }

        // rel vectors for neighbors 1..9 (drop self), phi
        float rx[9], ry[9], rz[9], ph[9];
        #pragma unroll
        for (int e = 0; e < 9; ++e) {
            float4 c = sx[midx[e+1]];
            rx[e] = c.x - qx; ry[e] = c.y - qy; rz[e] = c.z - qz;
            ph[e] = atan2f(ry[e], rx[e]);
        }

        // stable ascending bubble sort on phi (matches stable jnp.argsort)
        #pragma unroll
        for (int p = 0; p < 8; ++p) {
            #pragma unroll
            for (int u = 0; u < 8; ++u) {
                if (ph[u+1] < ph[u]) {
                    float t;
                    t = ph[u]; ph[u] = ph[u+1]; ph[u+1] = t;
                    t = rx[u]; rx[u] = rx[u+1]; rx[u+1] = t;
                    t = ry[u]; ry[u] = ry[u+1]; ry[u+1] = t;
                    t = rz[u]; rz[u] = rz[u+1]; rz[u+1] = t;
                }
            }
        }

        float sgn = 1.0f;
        const int base = ((b * NN + n) * KK) * 10;
        #pragma unroll
        for (int e = 0; e < 9; ++e) {
            const int e2 = (e + 1 == 9) ? 0 : e + 1;
            float ax = rx[e],  ay = ry[e],  az = rz[e];
            float bx = rx[e2], by = ry[e2], bz = rz[e2];
            float cx = 0.5f * (ax + bx), cy = 0.5f * (ay + by), cz = 0.5f * (az + bz);
            float nx = ay*bz - az*by;
            float ny = az*bx - ax*bz;
            float nz = ax*by - ay*bx;
            float nnv = sqrtf(nx*nx + ny*ny + nz*nz);
            float ri = 1.0f / (nnv + 1e-6f);
            nx *= ri; ny *= ri; nz *= ri;
            if (e == 0) sgn = (nx > 0.0f) ? 1.0f : -1.0f;
            nx *= sgn; ny *= sgn; nz *= sgn;
            float pos = (nx*cx + ny*cy + nz*cz) / sqrtf(3.0f);
            float dv = ax*bx + ay*by + az*bz;
            float nA = sqrtf(ax*ax + ay*ay + az*az);
            float nB = sqrtf(bx*bx + by*by + bz*bz);
            float cv = dv / (nA * nB + 1e-8f);
            cv = fminf(1.0f, fmaxf(-1.0f, cv));
            float ang = acosf(cv);
            float f[10] = {cx, cy, cz, nx, ny, nz, pos, ang, nA, nB};
            #pragma unroll
            for (int o = 0; o < 10; ++o) {
                float h = sb[o];
                #pragma unroll
                for (int i = 0; i < 10; ++i) h = fmaf(f[i], sW[o*10+i], h);
                g_h1[base + e*10 + o] = h;
                ls[o] += h;
                ls2[o] = fmaf(h, h, ls2[o]);
            }
        }
    }

    // block reduction of BN1 partials (reuse sx region after sync)
    __syncthreads();
    float* sred = (float*)sx;   // 8 warps * 20 floats
    const int lane = tid & 31, wid = tid >> 5;
    #pragma unroll
    for (int t = 0; t < 20; ++t) {
        float v = (t < 10) ? ls[t] : ls2[t-10];
        #pragma unroll
        for (int off = 16; off > 0; off >>= 1) v += __shfl_down_sync(0xffffffffu, v, off);
        if (lane == 0) sred[wid*20 + t] = v;
    }
    __syncthreads();
    if (tid < 20) {
        float s = 0.0f;
        #pragma unroll
        for (int w = 0; w < 8; ++w) s += sred[w*20 + tid];
        g_p1[(blockIdx.y * gridDim.x + blockIdx.x) * 20 + tid] = s;
    }
}

// ---------------------------------------------------------------------------
// Stats reduce: partials -> mu, rsqrt(var + eps). <<<1,160>>>
// ---------------------------------------------------------------------------
__global__ void stats_kernel(int which) {
    const float* part = which ? g_p2 : g_p1;
    const int nb = which ? NB3 : NB1;
    float* stats = which ? g_s2 : g_s1;
    __shared__ double sdd[20][8];
    __shared__ float sd[20];
    const int tid = threadIdx.x;
    if (tid < 160) {
        const int col = tid >> 3, sl = tid & 7;
        double s = 0.0;
        for (int i = sl; i < nb; i += 8) s += (double)part[i*20 + col];
        sdd[col][sl] = s;
    }
    __syncthreads();
    if (tid < 20) {
        double s = 0.0;
        #pragma unroll
        for (int i = 0; i < 8; ++i) s += sdd[tid][i];
        sd[tid] = (float)(s / (double)ROWS);
    }
    __syncthreads();
    if (tid < 10) {
        float mu = sd[tid];
        float var = fmaxf(sd[tid+10] - mu*mu, 0.0f);
        stats[tid] = mu;
        stats[10+tid] = rsqrtf(var + 1e-5f);
    }
}

// ---------------------------------------------------------------------------
// Kernel 3: BN1 + ReLU + linear2 + BN2 partial stats. <<<NB3,256>>>
// ---------------------------------------------------------------------------
__global__ void mlp2_kernel(const float* __restrict__ g1v, const float* __restrict__ be1,
                            const float* __restrict__ W2, const float* __restrict__ b2) {
    __shared__ float sW[100], sb[10], smu[10], sinv[10], sg[10], sbe[10];
    __shared__ float sred[8*20];
    const int tid = threadIdx.x;
    if (tid < 100) sW[tid] = W2[tid];
    if (tid < 10) {
        sb[tid] = b2[tid]; smu[tid] = g_s1[tid]; sinv[tid] = g_s1[10+tid];
        sg[tid] = g1v[tid]; sbe[tid] = be1[tid];
    }
    __syncthreads();
    float ls[10], ls2[10];
    #pragma unroll
    for (int o = 0; o < 10; ++o) { ls[o] = 0.0f; ls2[o] = 0.0f; }
    const int stride = gridDim.x * blockDim.x;
    for (int r = blockIdx.x * blockDim.x + tid; r < ROWS; r += stride) {
        float a[10];
        #pragma unroll
        for (int i = 0; i < 10; ++i) {
            float h = g_h1[r*10 + i];
            h = ((h - smu[i]) * sinv[i]) * sg[i] + sbe[i];
            a[i] = fmaxf(h, 0.0f);
        }
        #pragma unroll
        for (int o = 0; o < 10; ++o) {
            float h = sb[o];
            #pragma unroll
            for (int i = 0; i < 10; ++i) h = fmaf(a[i], sW[o*10+i], h);
            g_h2[r*10 + o] = h;
            ls[o] += h;
            ls2[o] = fmaf(h, h, ls2[o]);
        }
    }
    const int lane = tid & 31, wid = tid >> 5;
    #pragma unroll
    for (int t = 0; t < 20; ++t) {
        float v = (t < 10) ? ls[t] : ls2[t-10];
        #pragma unroll
        for (int off = 16; off > 0; off >>= 1) v += __shfl_down_sync(0xffffffffu, v, off);
        if (lane == 0) sred[wid*20 + t] = v;
    }
    __syncthreads();
    if (tid < 20) {
        float s = 0.0f;
        #pragma unroll
        for (int w = 0; w < 8; ++w) s += sred[w*20 + tid];
        g_p2[blockIdx.x*20 + tid] = s;
    }
}

// ---------------------------------------------------------------------------
// Kernel 5: BN2 + ReLU + max over k. <<<BB*NN/256, 256>>>
// ---------------------------------------------------------------------------
__global__ void out_kernel(const float* __restrict__ g2v, const float* __restrict__ be2,
                           float* __restrict__ out) {
    __shared__ float smu[10], sinv[10], sg[10], sbe[10];
    const int tid = threadIdx.x;
    if (tid < 10) {
        smu[tid] = g_s2[tid]; sinv[tid] = g_s2[10+tid];
        sg[tid] = g2v[tid]; sbe[tid] = be2[tid];
    }
    __syncthreads();
    const int p = blockIdx.x * blockDim.x + tid;
    float m[10];
    #pragma unroll
    for (int o = 0; o < 10; ++o) m[o] = 0.0f;  // relu outputs are >= 0
    const int base = p * KK * 10;
    #pragma unroll
    for (int e = 0; e < 9; ++e) {
        #pragma unroll
        for (int o = 0; o < 10; ++o) {
            float h = g_h2[base + e*10 + o];
            float y = fmaxf(((h - smu[o]) * sinv[o]) * sg[o] + sbe[o], 0.0f);
            m[o] = fmaxf(m[o], y);
        }
    }
    #pragma unroll
    for (int o = 0; o < 10; ++o) out[p*10 + o] = m[o];
}

// ---------------------------------------------------------------------------
extern "C" void kernel_launch(void* const* d_in, const int* in_sizes, int n_in,
                              void* d_out, int out_size) {
    (void)in_sizes; (void)n_in; (void)out_size;
    const float* x   = (const float*)d_in[0];
    const float* W1  = (const float*)d_in[1];
    const float* b1  = (const float*)d_in[2];
    const float* g1  = (const float*)d_in[3];
    const float* be1 = (const float*)d_in[4];
    const float* W2  = (const float*)d_in[5];
    const float* b2  = (const float*)d_in[6];
    const float* g2  = (const float*)d_in[7];
    const float* be2 = (const float*)d_in[8];
    float* out = (float*)d_out;

    const int smem1 = NN * 16 + 110 * 4 + QPB * SLICES * 10 * 8;
    cudaFuncSetAttribute(knn_feat_kernel, cudaFuncAttributeMaxDynamicSharedMemorySize, smem1);

    dim3 grid1(NN / QPB, BB);
    knn_feat_kernel<<<grid1, 256, smem1>>>(x, W1, b1);
    stats_kernel<<<1, 160>>>(0);
    mlp2_kernel<<<NB3, 256>>>(g1, be1, W2, b2);
    stats_kernel<<<1, 160>>>(1);
    out_kernel<<<(BB*NN)/256, 256>>>(g2, be2, out);
}

// round 4
// speedup vs baseline: 1.2948x; 1.2948x over previous
#include <cuda_runtime.h>
#include <math.h>
#include <float.h>

#define BB 8
#define NN 4096
#define KK 9
#define ROWS (BB*NN*KK)   /* 294912 */
#define QB 32             /* queries per block */
#define QW 4              /* queries per warp (8 warps * 4 = 32) */
#define NB1 (BB*NN/QB)    /* 1024 knn blocks */
#define NB3 512

// Scratch (allocation-free: __device__ globals)
__device__ float g_h1[ROWS*10];
__device__ float g_h2[ROWS*10];
__device__ float g_p1[NB1*20];
__device__ float g_p2[NB3*20];
__device__ float g_s1[20];   // mu[10], inv[10]
__device__ float g_s2[20];

__device__ __forceinline__ bool dless(float d1, int j1, float d2, int j2) {
    return d1 < d2 || (d1 == d2 && j1 < j2);
}

// ---------------------------------------------------------------------------
// Kernel 1: warp-per-query ballot kNN + features + linear1 + BN1 partials
// grid (NN/QB, BB), block 256
// smem: sx[NN] float4 | sW[100] | sb[10] | s_nbr[QB*9] int
// ---------------------------------------------------------------------------
__global__ __launch_bounds__(256) void knn_feat_kernel(const float* __restrict__ x,
                                                       const float* __restrict__ W1,
                                                       const float* __restrict__ b1) {
    extern __shared__ float4 sx[];                 // [NN]  64KB
    float* sW   = (float*)&sx[NN];                 // 100
    float* sb   = sW + 100;                        // 10
    int*   s_nbr = (int*)(sb + 10);                // QB*9 ints

    const int tid = threadIdx.x;
    const int lane = tid & 31;
    const int w = tid >> 5;
    const int b = blockIdx.y;
    const float* xb = x + (size_t)b * NN * 3;

    for (int j = tid; j < NN; j += blockDim.x) {
        float xx = xb[j*3+0], yy = xb[j*3+1], zz = xb[j*3+2];
        float ww = fmaf(zz, zz, fmaf(yy, yy, xx*xx));
        sx[j] = make_float4(xx, yy, zz, ww);
    }
    if (tid < 100) sW[tid] = W1[tid];
    if (tid < 10)  sb[tid] = b1[tid];
    __syncthreads();

    // ---------------- Phase B: warp-per-query ballot scan ----------------
    for (int r = 0; r < QW; ++r) {
        const int qloc = w * QW + r;
        const int n = blockIdx.x * QB + qloc;
        const float4 qv = sx[n];
        const float qx = qv.x, qy = qv.y, qz = qv.z, q2 = qv.w;

        // distributed sorted top-10: lane t<10 holds slot t (ascending)
        float sd = FLT_MAX; int si = 0x7fffffff;
        // replicated threshold = slot 9
        float thr_d = FLT_MAX; int thr_j = 0x7fffffff;

        for (int j0 = 0; j0 < NN; j0 += 32) {
            const int j = j0 + lane;
            float4 c = sx[j];
            float dot = fmaf(qz, c.z, fmaf(qy, c.y, qx * c.x));
            // match reference: (x2n + x2m) - 2*dot, no fma contraction on combine
            float d = __fsub_rn(__fadd_rn(q2, c.w), __fmul_rn(2.0f, dot));
            unsigned mask = __ballot_sync(0xffffffffu, dless(d, j, thr_d, thr_j));
            while (mask) {
                const int src = __ffs(mask) - 1;
                mask &= mask - 1;
                const float nd = __shfl_sync(0xffffffffu, d, src);
                const int   nj = j0 + src;
                // warp-SIMD sorted insert: shift slots >= pos down by one
                const float pd = __shfl_up_sync(0xffffffffu, sd, 1);
                const int   pi = __shfl_up_sync(0xffffffffu, si, 1);
                const bool pcur  = dless(nd, nj, sd, si);
                const bool pprev = (lane > 0) && dless(nd, nj, pd, pi);
                if (pcur) { sd = pprev ? pd : nd; si = pprev ? pi : nj; }
                // refresh replicated threshold from slot 9
                thr_d = __shfl_sync(0xffffffffu, sd, 9);
                thr_j = __shfl_sync(0xffffffffu, si, 9);
            }
        }
        // slots 1..9 = neighbors (slot 0 = self)
        if (lane >= 1 && lane < 10) s_nbr[qloc * 9 + (lane - 1)] = si;
    }
    __syncthreads();

    // ---------------- Phase C: features + linear1 (1 thread/query) -------
    float ls[10], ls2[10];
    #pragma unroll
    for (int o = 0; o < 10; ++o) { ls[o] = 0.0f; ls2[o] = 0.0f; }

    if (tid < QB) {
        const int q = tid;
        const int n = blockIdx.x * QB + q;
        const float4 qv = sx[n];
        const float qx = qv.x, qy = qv.y, qz = qv.z;

        float rx[9], ry[9], rz[9], ph[9];
        #pragma unroll
        for (int e = 0; e < 9; ++e) {
            float4 c = sx[s_nbr[q*9 + e]];
            rx[e] = c.x - qx; ry[e] = c.y - qy; rz[e] = c.z - qz;
            ph[e] = atan2f(ry[e], rx[e]);
        }

        // stable ascending bubble sort on phi (matches stable jnp.argsort)
        #pragma unroll
        for (int p = 0; p < 8; ++p) {
            #pragma unroll
            for (int u = 0; u < 8; ++u) {
                if (ph[u+1] < ph[u]) {
                    float t;
                    t = ph[u]; ph[u] = ph[u+1]; ph[u+1] = t;
                    t = rx[u]; rx[u] = rx[u+1]; rx[u+1] = t;
                    t = ry[u]; ry[u] = ry[u+1]; ry[u+1] = t;
                    t = rz[u]; rz[u] = rz[u+1]; rz[u+1] = t;
                }
            }
        }

        float sgn = 1.0f;
        const int base = ((b * NN + n) * KK) * 10;
        #pragma unroll
        for (int e = 0; e < 9; ++e) {
            const int e2 = (e + 1 == 9) ? 0 : e + 1;
            float ax = rx[e],  ay = ry[e],  az = rz[e];
            float bx = rx[e2], by = ry[e2], bz = rz[e2];
            float cx = 0.5f * (ax + bx), cy = 0.5f * (ay + by), cz = 0.5f * (az + bz);
            float nx = ay*bz - az*by;
            float ny = az*bx - ax*bz;
            float nz = ax*by - ay*bx;
            float nnv = sqrtf(nx*nx + ny*ny + nz*nz);
            float ri = 1.0f / (nnv + 1e-6f);
            nx *= ri; ny *= ri; nz *= ri;
            if (e == 0) sgn = (nx > 0.0f) ? 1.0f : -1.0f;
            nx *= sgn; ny *= sgn; nz *= sgn;
            float pos = (nx*cx + ny*cy + nz*cz) / sqrtf(3.0f);
            float dv = ax*bx + ay*by + az*bz;
            float nA = sqrtf(ax*ax + ay*ay + az*az);
            float nB = sqrtf(bx*bx + by*by + bz*bz);
            float cv = dv / (nA * nB + 1e-8f);
            cv = fminf(1.0f, fmaxf(-1.0f, cv));
            float ang = acosf(cv);
            float f[10] = {cx, cy, cz, nx, ny, nz, pos, ang, nA, nB};
            #pragma unroll
            for (int o = 0; o < 10; ++o) {
                float h = sb[o];
                #pragma unroll
                for (int i = 0; i < 10; ++i) h = fmaf(f[i], sW[o*10+i], h);
                g_h1[base + e*10 + o] = h;
                ls[o] += h;
                ls2[o] = fmaf(h, h, ls2[o]);
            }
        }
    }

    // block reduction of BN1 partials (reuse sx region after sync)
    __syncthreads();
    float* sred = (float*)sx;   // 8 warps * 20 floats
    #pragma unroll
    for (int t = 0; t < 20; ++t) {
        float v = (t < 10) ? ls[t] : ls2[t-10];
        #pragma unroll
        for (int off = 16; off > 0; off >>= 1) v += __shfl_down_sync(0xffffffffu, v, off);
        if (lane == 0) sred[w*20 + t] = v;
    }
    __syncthreads();
    if (tid < 20) {
        float s = 0.0f;
        #pragma unroll
        for (int ww = 0; ww < 8; ++ww) s += sred[ww*20 + tid];
        g_p1[(blockIdx.y * gridDim.x + blockIdx.x) * 20 + tid] = s;
    }
}

// ---------------------------------------------------------------------------
// Stats reduce: partials -> mu, rsqrt(var + eps). <<<1,160>>>
// ---------------------------------------------------------------------------
__global__ void stats_kernel(int which) {
    const float* part = which ? g_p2 : g_p1;
    const int nb = which ? NB3 : NB1;
    float* stats = which ? g_s2 : g_s1;
    __shared__ double sdd[20][8];
    __shared__ float sd[20];
    const int tid = threadIdx.x;
    if (tid < 160) {
        const int col = tid >> 3, sl = tid & 7;
        double s = 0.0;
        for (int i = sl; i < nb; i += 8) s += (double)part[i*20 + col];
        sdd[col][sl] = s;
    }
    __syncthreads();
    if (tid < 20) {
        double s = 0.0;
        #pragma unroll
        for (int i = 0; i < 8; ++i) s += sdd[tid][i];
        sd[tid] = (float)(s / (double)ROWS);
    }
    __syncthreads();
    if (tid < 10) {
        float mu = sd[tid];
        float var = fmaxf(sd[tid+10] - mu*mu, 0.0f);
        stats[tid] = mu;
        stats[10+tid] = rsqrtf(var + 1e-5f);
    }
}

// ---------------------------------------------------------------------------
// Kernel 3: BN1 + ReLU + linear2 + BN2 partial stats. <<<NB3,256>>>
// ---------------------------------------------------------------------------
__global__ void mlp2_kernel(const float* __restrict__ g1v, const float* __restrict__ be1,
                            const float* __restrict__ W2, const float* __restrict__ b2) {
    __shared__ float sW[100], sb[10], smu[10], sinv[10], sg[10], sbe[10];
    __shared__ float sred[8*20];
    const int tid = threadIdx.x;
    if (tid < 100) sW[tid] = W2[tid];
    if (tid < 10) {
        sb[tid] = b2[tid]; smu[tid] = g_s1[tid]; sinv[tid] = g_s1[10+tid];
        sg[tid] = g1v[tid]; sbe[tid] = be1[tid];
    }
    __syncthreads();
    float ls[10], ls2[10];
    #pragma unroll
    for (int o = 0; o < 10; ++o) { ls[o] = 0.0f; ls2[o] = 0.0f; }
    const int stride = gridDim.x * blockDim.x;
    for (int r = blockIdx.x * blockDim.x + tid; r < ROWS; r += stride) {
        float a[10];
        #pragma unroll
        for (int i = 0; i < 10; ++i) {
            float h = g_h1[r*10 + i];
            h = ((h - smu[i]) * sinv[i]) * sg[i] + sbe[i];
            a[i] = fmaxf(h, 0.0f);
        }
        #pragma unroll
        for (int o = 0; o < 10; ++o) {
            float h = sb[o];
            #pragma unroll
            for (int i = 0; i < 10; ++i) h = fmaf(a[i], sW[o*10+i], h);
            g_h2[r*10 + o] = h;
            ls[o] += h;
            ls2[o] = fmaf(h, h, ls2[o]);
        }
    }
    const int lane = tid & 31, wid = tid >> 5;
    #pragma unroll
    for (int t = 0; t < 20; ++t) {
        float v = (t < 10) ? ls[t] : ls2[t-10];
        #pragma unroll
        for (int off = 16; off > 0; off >>= 1) v += __shfl_down_sync(0xffffffffu, v, off);
        if (lane == 0) sred[wid*20 + t] = v;
    }
    __syncthreads();
    if (tid < 20) {
        float s = 0.0f;
        #pragma unroll
        for (int w = 0; w < 8; ++w) s += sred[w*20 + tid];
        g_p2[blockIdx.x*20 + tid] = s;
    }
}

// ---------------------------------------------------------------------------
// Kernel 5: BN2 + ReLU + max over k. <<<BB*NN/256, 256>>>
// ---------------------------------------------------------------------------
__global__ void out_kernel(const float* __restrict__ g2v, const float* __restrict__ be2,
                           float* __restrict__ out) {
    __shared__ float smu[10], sinv[10], sg[10], sbe[10];
    const int tid = threadIdx.x;
    if (tid < 10) {
        smu[tid] = g_s2[tid]; sinv[tid] = g_s2[10+tid];
        sg[tid] = g2v[tid]; sbe[tid] = be2[tid];
    }
    __syncthreads();
    const int p = blockIdx.x * blockDim.x + tid;
    float m[10];
    #pragma unroll
    for (int o = 0; o < 10; ++o) m[o] = 0.0f;  // relu outputs are >= 0
    const int base = p * KK * 10;
    #pragma unroll
    for (int e = 0; e < 9; ++e) {
        #pragma unroll
        for (int o = 0; o < 10; ++o) {
            float h = g_h2[base + e*10 + o];
            float y = fmaxf(((h - smu[o]) * sinv[o]) * sg[o] + sbe[o], 0.0f);
            m[o] = fmaxf(m[o], y);
        }
    }
    #pragma unroll
    for (int o = 0; o < 10; ++o) out[p*10 + o] = m[o];
}

// ---------------------------------------------------------------------------
extern "C" void kernel_launch(void* const* d_in, const int* in_sizes, int n_in,
                              void* d_out, int out_size) {
    (void)in_sizes; (void)n_in; (void)out_size;
    const float* x   = (const float*)d_in[0];
    const float* W1  = (const float*)d_in[1];
    const float* b1  = (const float*)d_in[2];
    const float* g1  = (const float*)d_in[3];
    const float* be1 = (const float*)d_in[4];
    const float* W2  = (const float*)d_in[5];
    const float* b2  = (const float*)d_in[6];
    const float* g2  = (const float*)d_in[7];
    const float* be2 = (const float*)d_in[8];
    float* out = (float*)d_out;

    const int smem1 = NN * 16 + 110 * 4 + QB * 9 * 4;
    cudaFuncSetAttribute(knn_feat_kernel, cudaFuncAttributeMaxDynamicSharedMemorySize, smem1);

    dim3 grid1(NN / QB, BB);
    knn_feat_kernel<<<grid1, 256, smem1>>>(x, W1, b1);
    stats_kernel<<<1, 160>>>(0);
    mlp2_kernel<<<NB3, 256>>>(g1, be1, W2, b2);
    stats_kernel<<<1, 160>>>(1);
    out_kernel<<<(BB*NN)/256, 256>>>(g2, be2, out);
}

// round 5
// speedup vs baseline: 1.6605x; 1.2824x over previous
#include <cuda_runtime.h>
#include <math.h>
#include <float.h>

#define BB 8
#define NN 4096
#define KK 9
#define ROWS (BB*NN*KK)   /* 294912 */
#define QB 32             /* queries per block */
#define QW 4              /* queries per warp (8 warps * 4 = 32) */
#define CAP 64            /* survivor capacity per warp */
#define NB1 (BB*NN/QB)    /* 1024 knn blocks */
#define NB3 512

// Scratch (allocation-free: __device__ globals)
__device__ float g_h1[ROWS*10];
__device__ float g_h2[ROWS*10];
__device__ float g_p1[NB1*20];
__device__ float g_p2[NB3*20];
__device__ float g_s1[20];   // mu[10], inv[10]
__device__ float g_s2[20];

__device__ __forceinline__ bool dless(float d1, int j1, float d2, int j2) {
    return d1 < d2 || (d1 == d2 && j1 < j2);
}

// Warp-distributed sorted top-10 insert: lane t<10 holds slot t (ascending lex).
// Validated in R4 (passed with rel_err 2.7e-7).
__device__ __forceinline__ void warp_insert(float nd, int nj, float& sd, int& si,
                                            const int lane) {
    const float pd = __shfl_up_sync(0xffffffffu, sd, 1);
    const int   pi = __shfl_up_sync(0xffffffffu, si, 1);
    const bool pcur  = dless(nd, nj, sd, si);
    const bool pprev = (lane > 0) && dless(nd, nj, pd, pi);
    if (pcur) { sd = pprev ? pd : nd; si = pprev ? pi : nj; }
}

__global__ void warm_kernel() {}   // shifts ncu -s window onto knn_feat_kernel

// ---------------------------------------------------------------------------
// Kernel 1: threshold-filter kNN + features + linear1 + BN1 partials
// grid (NN/QB, BB), block 256
// ---------------------------------------------------------------------------
__global__ __launch_bounds__(256) void knn_feat_kernel(const float* __restrict__ x,
                                                       const float* __restrict__ W1,
                                                       const float* __restrict__ b1) {
    extern __shared__ float4 sx[];                   // [NN]  64KB
    float* sW    = (float*)&sx[NN];                  // 100
    float* sb    = sW + 100;                         // 10
    int*   s_nbr = (int*)(sb + 10);                  // QB*9
    float* s_svd = (float*)(s_nbr + QB*9);           // 8 warps * CAP
    int*   s_svj = (int*)(s_svd + 8*CAP);            // 8 warps * CAP

    const int tid = threadIdx.x;
    const int lane = tid & 31;
    const int w = tid >> 5;
    const int b = blockIdx.y;
    const float* xb = x + (size_t)b * NN * 3;

    for (int j = tid; j < NN; j += blockDim.x) {
        float xx = xb[j*3+0], yy = xb[j*3+1], zz = xb[j*3+2];
        float ww = fmaf(zz, zz, fmaf(yy, yy, xx*xx));
        sx[j] = make_float4(xx, yy, zz, ww);
    }
    if (tid < 100) sW[tid] = W1[tid];
    if (tid < 10)  sb[tid] = b1[tid];
    __syncthreads();

    float* svd = s_svd + w * CAP;
    int*   svj = s_svj + w * CAP;

    // ---------------- Phase B: filtered kNN, warp per query ----------------
    for (int r = 0; r < QW; ++r) {
        const int qloc = w * QW + r;
        const int n = blockIdx.x * QB + qloc;
        const float4 qv = sx[n];
        const float qx = qv.x, qy = qv.y, qz = qv.z, q2 = qv.w;

        // --- Pass 0: per-lane (min, argmin) over its 128 candidates -------
        float m0 = FLT_MAX, m1 = FLT_MAX, m2 = FLT_MAX, m3 = FLT_MAX;
        int   a0 = 0x7fffffff, a1 = 0x7fffffff, a2 = 0x7fffffff, a3 = 0x7fffffff;
        for (int i = 0; i < 128; i += 4) {
            #pragma unroll
            for (int u = 0; u < 4; ++u) {
                const int j = (i + u) * 32 + lane;
                float4 c = sx[j];
                float dot = fmaf(qz, c.z, fmaf(qy, c.y, qx * c.x));
                // match reference: (x2n + x2m) - 2*dot, no fma contraction
                float d = __fsub_rn(__fadd_rn(q2, c.w), __fmul_rn(2.0f, dot));
                bool cc;
                if (u == 0) { cc = d < m0; m0 = cc ? d : m0; a0 = cc ? j : a0; }
                if (u == 1) { cc = d < m1; m1 = cc ? d : m1; a1 = cc ? j : a1; }
                if (u == 2) { cc = d < m2; m2 = cc ? d : m2; a2 = cc ? j : a2; }
                if (u == 3) { cc = d < m3; m3 = cc ? d : m3; a3 = cc ? j : a3; }
            }
        }
        // combine 4 accumulators (lex, so exact tie-break by index)
        float lm = m0; int la = a0;
        if (dless(m1, a1, lm, la)) { lm = m1; la = a1; }
        if (dless(m2, a2, lm, la)) { lm = m2; la = a2; }
        if (dless(m3, a3, lm, la)) { lm = m3; la = a3; }

        // --- insert 32 lane-min pairs -> T = 10th smallest lane-min -------
        float sd = FLT_MAX; int si = 0x7fffffff;
        #pragma unroll 8
        for (int s = 0; s < 32; ++s) {
            const float nd = __shfl_sync(0xffffffffu, lm, s);
            const int   nj = __shfl_sync(0xffffffffu, la, s);
            warp_insert(nd, nj, sd, si, lane);
        }
        const float Td = __shfl_sync(0xffffffffu, sd, 9);
        const int   Tj = __shfl_sync(0xffffffffu, si, 9);

        // --- Pass 1: filter + compact survivors (in increasing j order) ---
        int cnt = 0;
        for (int i = 0; i < 128; ++i) {
            const int j = i * 32 + lane;
            float4 c = sx[j];
            float dot = fmaf(qz, c.z, fmaf(qy, c.y, qx * c.x));
            float d = __fsub_rn(__fadd_rn(q2, c.w), __fmul_rn(2.0f, dot));
            const bool keep = !dless(Td, Tj, d, j);   // lex (d,j) <= (Td,Tj)
            const unsigned mask = __ballot_sync(0xffffffffu, keep);
            if (mask) {
                const int pos = cnt + __popc(mask & ((1u << lane) - 1u));
                if (keep && pos < CAP) { svd[pos] = d; svj[pos] = j; }
                cnt += __popc(mask);
            }
        }

        // --- Pass 2: exact top-10 over survivors --------------------------
        sd = FLT_MAX; si = 0x7fffffff;
        if (cnt <= CAP) {
            for (int s = 0; s < cnt; ++s) {
                const float nd = svd[s];   // broadcast LDS
                const int   nj = svj[s];
                warp_insert(nd, nj, sd, si, lane);
            }
        } else {
            // fallback (probability ~0): exact full ballot scan (R4 method)
            float thr_d = FLT_MAX; int thr_j = 0x7fffffff;
            for (int j0 = 0; j0 < NN; j0 += 32) {
                const int j = j0 + lane;
                float4 c = sx[j];
                float dot = fmaf(qz, c.z, fmaf(qy, c.y, qx * c.x));
                float d = __fsub_rn(__fadd_rn(q2, c.w), __fmul_rn(2.0f, dot));
                unsigned mask = __ballot_sync(0xffffffffu, dless(d, j, thr_d, thr_j));
                while (mask) {
                    const int src = __ffs(mask) - 1;
                    mask &= mask - 1;
                    const float nd = __shfl_sync(0xffffffffu, d, src);
                    const int   nj = j0 + src;
                    warp_insert(nd, nj, sd, si, lane);
                    thr_d = __shfl_sync(0xffffffffu, sd, 9);
                    thr_j = __shfl_sync(0xffffffffu, si, 9);
                }
            }
        }
        // slots 1..9 = neighbors (slot 0 = self/nearest)
        if (lane >= 1 && lane < 10) s_nbr[qloc * 9 + (lane - 1)] = si;
    }
    __syncthreads();

    // ---------------- Phase C: features + linear1 (1 thread/query) -------
    float ls[10], ls2[10];
    #pragma unroll
    for (int o = 0; o < 10; ++o) { ls[o] = 0.0f; ls2[o] = 0.0f; }

    if (tid < QB) {
        const int q = tid;
        const int n = blockIdx.x * QB + q;
        const float4 qv = sx[n];
        const float qx = qv.x, qy = qv.y, qz = qv.z;

        float rx[9], ry[9], rz[9], ph[9];
        #pragma unroll
        for (int e = 0; e < 9; ++e) {
            float4 c = sx[s_nbr[q*9 + e]];
            rx[e] = c.x - qx; ry[e] = c.y - qy; rz[e] = c.z - qz;
            ph[e] = atan2f(ry[e], rx[e]);
        }

        // stable ascending bubble sort on phi (matches stable jnp.argsort)
        #pragma unroll
        for (int p = 0; p < 8; ++p) {
            #pragma unroll
            for (int u = 0; u < 8; ++u) {
                if (ph[u+1] < ph[u]) {
                    float t;
                    t = ph[u]; ph[u] = ph[u+1]; ph[u+1] = t;
                    t = rx[u]; rx[u] = rx[u+1]; rx[u+1] = t;
                    t = ry[u]; ry[u] = ry[u+1]; ry[u+1] = t;
                    t = rz[u]; rz[u] = rz[u+1]; rz[u+1] = t;
                }
            }
        }

        float sgn = 1.0f;
        const int base = ((b * NN + n) * KK) * 10;
        #pragma unroll
        for (int e = 0; e < 9; ++e) {
            const int e2 = (e + 1 == 9) ? 0 : e + 1;
            float ax = rx[e],  ay = ry[e],  az = rz[e];
            float bx = rx[e2], by = ry[e2], bz = rz[e2];
            float cx = 0.5f * (ax + bx), cy = 0.5f * (ay + by), cz = 0.5f * (az + bz);
            float nx = ay*bz - az*by;
            float ny = az*bx - ax*bz;
            float nz = ax*by - ay*bx;
            float nnv = sqrtf(nx*nx + ny*ny + nz*nz);
            float ri = 1.0f / (nnv + 1e-6f);
            nx *= ri; ny *= ri; nz *= ri;
            if (e == 0) sgn = (nx > 0.0f) ? 1.0f : -1.0f;
            nx *= sgn; ny *= sgn; nz *= sgn;
            float pos = (nx*cx + ny*cy + nz*cz) / sqrtf(3.0f);
            float dv = ax*bx + ay*by + az*bz;
            float nA = sqrtf(ax*ax + ay*ay + az*az);
            float nB = sqrtf(bx*bx + by*by + bz*bz);
            float cv = dv / (nA * nB + 1e-8f);
            cv = fminf(1.0f, fmaxf(-1.0f, cv));
            float ang = acosf(cv);
            float f[10] = {cx, cy, cz, nx, ny, nz, pos, ang, nA, nB};
            #pragma unroll
            for (int o = 0; o < 10; ++o) {
                float h = sb[o];
                #pragma unroll
                for (int i = 0; i < 10; ++i) h = fmaf(f[i], sW[o*10+i], h);
                g_h1[base + e*10 + o] = h;
                ls[o] += h;
                ls2[o] = fmaf(h, h, ls2[o]);
            }
        }
    }

    // block reduction of BN1 partials (reuse sx region after sync)
    __syncthreads();
    float* sred = (float*)sx;   // 8 warps * 20 floats
    #pragma unroll
    for (int t = 0; t < 20; ++t) {
        float v = (t < 10) ? ls[t] : ls2[t-10];
        #pragma unroll
        for (int off = 16; off > 0; off >>= 1) v += __shfl_down_sync(0xffffffffu, v, off);
        if (lane == 0) sred[w*20 + t] = v;
    }
    __syncthreads();
    if (tid < 20) {
        float s = 0.0f;
        #pragma unroll
        for (int ww = 0; ww < 8; ++ww) s += sred[ww*20 + tid];
        g_p1[(blockIdx.y * gridDim.x + blockIdx.x) * 20 + tid] = s;
    }
}

// ---------------------------------------------------------------------------
// Stats reduce: partials -> mu, rsqrt(var + eps). <<<1,160>>>
// ---------------------------------------------------------------------------
__global__ void stats_kernel(int which) {
    const float* part = which ? g_p2 : g_p1;
    const int nb = which ? NB3 : NB1;
    float* stats = which ? g_s2 : g_s1;
    __shared__ double sdd[20][8];
    __shared__ float sd[20];
    const int tid = threadIdx.x;
    if (tid < 160) {
        const int col = tid >> 3, sl = tid & 7;
        double s = 0.0;
        for (int i = sl; i < nb; i += 8) s += (double)part[i*20 + col];
        sdd[col][sl] = s;
    }
    __syncthreads();
    if (tid < 20) {
        double s = 0.0;
        #pragma unroll
        for (int i = 0; i < 8; ++i) s += sdd[tid][i];
        sd[tid] = (float)(s / (double)ROWS);
    }
    __syncthreads();
    if (tid < 10) {
        float mu = sd[tid];
        float var = fmaxf(sd[tid+10] - mu*mu, 0.0f);
        stats[tid] = mu;
        stats[10+tid] = rsqrtf(var + 1e-5f);
    }
}

// ---------------------------------------------------------------------------
// Kernel 3: BN1 + ReLU + linear2 + BN2 partial stats. <<<NB3,256>>>
// ---------------------------------------------------------------------------
__global__ void mlp2_kernel(const float* __restrict__ g1v, const float* __restrict__ be1,
                            const float* __restrict__ W2, const float* __restrict__ b2) {
    __shared__ float sW[100], sb[10], smu[10], sinv[10], sg[10], sbe[10];
    __shared__ float sred[8*20];
    const int tid = threadIdx.x;
    if (tid < 100) sW[tid] = W2[tid];
    if (tid < 10) {
        sb[tid] = b2[tid]; smu[tid] = g_s1[tid]; sinv[tid] = g_s1[10+tid];
        sg[tid] = g1v[tid]; sbe[tid] = be1[tid];
    }
    __syncthreads();
    float ls[10], ls2[10];
    #pragma unroll
    for (int o = 0; o < 10; ++o) { ls[o] = 0.0f; ls2[o] = 0.0f; }
    const int stride = gridDim.x * blockDim.x;
    for (int r = blockIdx.x * blockDim.x + tid; r < ROWS; r += stride) {
        float a[10];
        #pragma unroll
        for (int i = 0; i < 10; ++i) {
            float h = g_h1[r*10 + i];
            h = ((h - smu[i]) * sinv[i]) * sg[i] + sbe[i];
            a[i] = fmaxf(h, 0.0f);
        }
        #pragma unroll
        for (int o = 0; o < 10; ++o) {
            float h = sb[o];
            #pragma unroll
            for (int i = 0; i < 10; ++i) h = fmaf(a[i], sW[o*10+i], h);
            g_h2[r*10 + o] = h;
            ls[o] += h;
            ls2[o] = fmaf(h, h, ls2[o]);
        }
    }
    const int lane = tid & 31, wid = tid >> 5;
    #pragma unroll
    for (int t = 0; t < 20; ++t) {
        float v = (t < 10) ? ls[t] : ls2[t-10];
        #pragma unroll
        for (int off = 16; off > 0; off >>= 1) v += __shfl_down_sync(0xffffffffu, v, off);
        if (lane == 0) sred[wid*20 + t] = v;
    }
    __syncthreads();
    if (tid < 20) {
        float s = 0.0f;
        #pragma unroll
        for (int w = 0; w < 8; ++w) s += sred[w*20 + tid];
        g_p2[blockIdx.x*20 + tid] = s;
    }
}

// ---------------------------------------------------------------------------
// Kernel 5: BN2 + ReLU + max over k. <<<BB*NN/256, 256>>>
// ---------------------------------------------------------------------------
__global__ void out_kernel(const float* __restrict__ g2v, const float* __restrict__ be2,
                           float* __restrict__ out) {
    __shared__ float smu[10], sinv[10], sg[10], sbe[10];
    const int tid = threadIdx.x;
    if (tid < 10) {
        smu[tid] = g_s2[tid]; sinv[tid] = g_s2[10+tid];
        sg[tid] = g2v[tid]; sbe[tid] = be2[tid];
    }
    __syncthreads();
    const int p = blockIdx.x * blockDim.x + tid;
    float m[10];
    #pragma unroll
    for (int o = 0; o < 10; ++o) m[o] = 0.0f;  // relu outputs are >= 0
    const int base = p * KK * 10;
    #pragma unroll
    for (int e = 0; e < 9; ++e) {
        #pragma unroll
        for (int o = 0; o < 10; ++o) {
            float h = g_h2[base + e*10 + o];
            float y = fmaxf(((h - smu[o]) * sinv[o]) * sg[o] + sbe[o], 0.0f);
            m[o] = fmaxf(m[o], y);
        }
    }
    #pragma unroll
    for (int o = 0; o < 10; ++o) out[p*10 + o] = m[o];
}

// ---------------------------------------------------------------------------
extern "C" void kernel_launch(void* const* d_in, const int* in_sizes, int n_in,
                              void* d_out, int out_size) {
    (void)in_sizes; (void)n_in; (void)out_size;
    const float* x   = (const float*)d_in[0];
    const float* W1  = (const float*)d_in[1];
    const float* b1  = (const float*)d_in[2];
    const float* g1  = (const float*)d_in[3];
    const float* be1 = (const float*)d_in[4];
    const float* W2  = (const float*)d_in[5];
    const float* b2  = (const float*)d_in[6];
    const float* g2  = (const float*)d_in[7];
    const float* be2 = (const float*)d_in[8];
    float* out = (float*)d_out;

    const int smem1 = NN * 16 + 110 * 4 + QB * 9 * 4 + 8 * CAP * 8;
    cudaFuncSetAttribute(knn_feat_kernel, cudaFuncAttributeMaxDynamicSharedMemorySize, smem1);

    warm_kernel<<<1, 32>>>();
    dim3 grid1(NN / QB, BB);
    knn_feat_kernel<<<grid1, 256, smem1>>>(x, W1, b1);
    stats_kernel<<<1, 160>>>(0);
    mlp2_kernel<<<NB3, 256>>>(g1, be1, W2, b2);
    stats_kernel<<<1, 160>>>(1);
    out_kernel<<<(BB*NN)/256, 256>>>(g2, be2, out);
}

// round 6
// speedup vs baseline: 4.2046x; 2.5322x over previous
#include <cuda_runtime.h>
#include <math.h>
#include <float.h>

#define BB 8
#define NN 4096
#define KK 9
#define ROWS (BB*NN*KK)   /* 294912 */
#define QB 32             /* queries per block (knn) */
#define QW 4              /* queries per warp */
#define CAP 32            /* survivor capacity per query */
#define NB2 256           /* feat kernel blocks */
#define NB3 512

// Scratch (allocation-free: __device__ globals)
__device__ int   g_nbr[BB*NN*KK];
__device__ float g_h1[ROWS*10];
__device__ float g_h2[ROWS*10];
__device__ float g_p1[NB2*20];
__device__ float g_p2[NB3*20];
__device__ float g_s1[20];   // mu[10], inv[10]
__device__ float g_s2[20];

__device__ __forceinline__ bool dless(float d1, int j1, float d2, int j2) {
    return d1 < d2 || (d1 == d2 && j1 < j2);
}

// Warp-distributed sorted top-10 insert (validated R4/R5): lane t holds slot t.
__device__ __forceinline__ void warp_insert(float nd, int nj, float& sd, int& si,
                                            const int lane) {
    const float pd = __shfl_up_sync(0xffffffffu, sd, 1);
    const int   pi = __shfl_up_sync(0xffffffffu, si, 1);
    const bool pcur  = dless(nd, nj, sd, si);
    const bool pprev = (lane > 0) && dless(nd, nj, pd, pi);
    if (pcur) { sd = pprev ? pd : nd; si = pprev ? pi : nj; }
}

// Full bitonic sort of 32 (d,j) pairs across lanes, ascending lex.
// 4 independent sorts interleaved for ILP.
__device__ __forceinline__ void bitonic32_4(float d[QW], int j[QW], const int lane) {
    #pragma unroll
    for (int k = 2; k <= 32; k <<= 1) {
        #pragma unroll
        for (int s = k >> 1; s > 0; s >>= 1) {
            const bool keepMin = (((lane & s) == 0) == ((lane & k) == 0));
            #pragma unroll
            for (int q = 0; q < QW; ++q) {
                const float od = __shfl_xor_sync(0xffffffffu, d[q], s);
                const int   oj = __shfl_xor_sync(0xffffffffu, j[q], s);
                const bool takeOther = (dless(od, oj, d[q], j[q]) == keepMin);
                d[q] = takeOther ? od : d[q];
                j[q] = takeOther ? oj : j[q];
            }
        }
    }
}

// ---------------------------------------------------------------------------
// Kernel 1: threshold-filter kNN, 4 queries per warp amortizing LDS.
// grid (NN/QB, BB), block 256. smem = sx[NN] float4 + survivors.
// ---------------------------------------------------------------------------
__global__ __launch_bounds__(256, 3) void knn_kernel(const float* __restrict__ x) {
    extern __shared__ float4 sx[];                   // [NN]  64KB
    float* s_svd = (float*)&sx[NN];                  // 8 warps * QW * CAP
    int*   s_svj = (int*)(s_svd + 8*QW*CAP);

    const int tid = threadIdx.x;
    const int lane = tid & 31;
    const int w = tid >> 5;
    const int b = blockIdx.y;
    const float* xb = x + (size_t)b * NN * 3;

    for (int j = tid; j < NN; j += blockDim.x) {
        float xx = xb[j*3+0], yy = xb[j*3+1], zz = xb[j*3+2];
        float ww = fmaf(zz, zz, fmaf(yy, yy, xx*xx));
        sx[j] = make_float4(xx, yy, zz, ww);
    }
    __syncthreads();

    float* svd = s_svd + w * (QW*CAP);
    int*   svj = s_svj + w * (QW*CAP);

    // query registers (4 per warp)
    const int n0 = blockIdx.x * QB + w * QW;
    float qx[QW], qy[QW], qz[QW], q2[QW];
    #pragma unroll
    for (int q = 0; q < QW; ++q) {
        const float4 qv = sx[n0 + q];
        qx[q] = qv.x; qy[q] = qv.y; qz[q] = qv.z; q2[q] = qv.w;
    }

    // --- Pass 0: per-lane lex-min over its 128 candidates, 4 queries ------
    float m[QW]; int a[QW];
    #pragma unroll
    for (int q = 0; q < QW; ++q) { m[q] = FLT_MAX; a[q] = 0x7fffffff; }
    for (int i = 0; i < 128; ++i) {
        const int j = i * 32 + lane;
        const float4 c = sx[j];
        #pragma unroll
        for (int q = 0; q < QW; ++q) {
            float dot = fmaf(qz[q], c.z, fmaf(qy[q], c.y, qx[q] * c.x));
            // match reference: (x2n + x2m) - 2*dot, no fma contraction
            float d = __fsub_rn(__fadd_rn(q2[q], c.w), __fmul_rn(2.0f, dot));
            const bool cc = d < m[q];      // strict <: keeps earliest j (lex)
            m[q] = cc ? d : m[q];
            a[q] = cc ? j : a[q];
        }
    }

    // --- threshold: sort 32 lane-mins; T = 10th smallest (lane 9) ---------
    bitonic32_4(m, a, lane);
    float Td[QW]; int Tj[QW];
    #pragma unroll
    for (int q = 0; q < QW; ++q) {
        Td[q] = __shfl_sync(0xffffffffu, m[q], 9);
        Tj[q] = __shfl_sync(0xffffffffu, a[q], 9);
    }

    // --- Pass 1: filter + compact survivors (increasing j order) ----------
    int cnt[QW];
    #pragma unroll
    for (int q = 0; q < QW; ++q) cnt[q] = 0;
    for (int i = 0; i < 128; ++i) {
        const int j = i * 32 + lane;
        const float4 c = sx[j];
        #pragma unroll
        for (int q = 0; q < QW; ++q) {
            float dot = fmaf(qz[q], c.z, fmaf(qy[q], c.y, qx[q] * c.x));
            float d = __fsub_rn(__fadd_rn(q2[q], c.w), __fmul_rn(2.0f, dot));
            const bool keep = !dless(Td[q], Tj[q], d, j);   // (d,j) <=lex T
            const unsigned mask = __ballot_sync(0xffffffffu, keep);
            if (mask) {
                const int pos = cnt[q] + __popc(mask & ((1u << lane) - 1u));
                if (keep && pos < CAP) { svd[q*CAP + pos] = d; svj[q*CAP + pos] = j; }
                cnt[q] += __popc(mask);
            }
        }
    }

    // --- Pass 2: gather survivors + one bitonic sort -> exact top-10 ------
    float dg[QW]; int jg[QW];
    #pragma unroll
    for (int q = 0; q < QW; ++q) {
        const bool v = lane < cnt[q] && lane < CAP;
        dg[q] = v ? svd[q*CAP + lane] : FLT_MAX;
        jg[q] = v ? svj[q*CAP + lane] : 0x7fffffff;
    }
    bitonic32_4(dg, jg, lane);

    #pragma unroll
    for (int q = 0; q < QW; ++q) {
        int resj = jg[q];
        if (cnt[q] > CAP) {
            // fallback (probability ~0): exact full ballot scan (R4 method)
            float sd = FLT_MAX; int si = 0x7fffffff;
            float thr_d = FLT_MAX; int thr_j = 0x7fffffff;
            for (int j0 = 0; j0 < NN; j0 += 32) {
                const int j = j0 + lane;
                float4 c = sx[j];
                float dot = fmaf(qz[q], c.z, fmaf(qy[q], c.y, qx[q] * c.x));
                float d = __fsub_rn(__fadd_rn(q2[q], c.w), __fmul_rn(2.0f, dot));
                unsigned mask = __ballot_sync(0xffffffffu, dless(d, j, thr_d, thr_j));
                while (mask) {
                    const int src = __ffs(mask) - 1;
                    mask &= mask - 1;
                    const float nd = __shfl_sync(0xffffffffu, d, src);
                    const int   nj = j0 + src;
                    warp_insert(nd, nj, sd, si, lane);
                    thr_d = __shfl_sync(0xffffffffu, sd, 9);
                    thr_j = __shfl_sync(0xffffffffu, si, 9);
                }
            }
            resj = si;
        }
        // slots 1..9 = neighbors (slot 0 dropped, as reference drops rel[...,0,:])
        if (lane >= 1 && lane < 10) {
            const int n = n0 + q;
            g_nbr[((size_t)b * NN + n) * KK + (lane - 1)] = resj;
        }
    }
}

// ---------------------------------------------------------------------------
// Kernel 2: features + linear1 + BN1 partials. <<<NB2,128>>> thread/query
// ---------------------------------------------------------------------------
__global__ __launch_bounds__(128) void feat_kernel(const float* __restrict__ x,
                                                   const float* __restrict__ W1,
                                                   const float* __restrict__ b1) {
    __shared__ float sW[100], sb[10];
    __shared__ float sred[4*20];
    const int tid = threadIdx.x;
    if (tid < 100) sW[tid] = W1[tid];
    if (tid < 10)  sb[tid] = b1[tid];
    __syncthreads();

    const int gid = blockIdx.x * blockDim.x + tid;     // 0..BB*NN-1
    const int b = gid >> 12;
    const int n = gid & (NN - 1);
    const float* xb = x + (size_t)b * NN * 3;

    const float qx = xb[n*3+0], qy = xb[n*3+1], qz = xb[n*3+2];

    float rx[9], ry[9], rz[9], ph[9];
    #pragma unroll
    for (int e = 0; e < 9; ++e) {
        const int idx = g_nbr[(size_t)gid * KK + e];
        rx[e] = xb[idx*3+0] - qx;
        ry[e] = xb[idx*3+1] - qy;
        rz[e] = xb[idx*3+2] - qz;
        ph[e] = atan2f(ry[e], rx[e]);
    }

    // stable ascending bubble sort on phi (matches stable jnp.argsort)
    #pragma unroll
    for (int p = 0; p < 8; ++p) {
        #pragma unroll
        for (int u = 0; u < 8; ++u) {
            if (ph[u+1] < ph[u]) {
                float t;
                t = ph[u]; ph[u] = ph[u+1]; ph[u+1] = t;
                t = rx[u]; rx[u] = rx[u+1]; rx[u+1] = t;
                t = ry[u]; ry[u] = ry[u+1]; ry[u+1] = t;
                t = rz[u]; rz[u] = rz[u+1]; rz[u+1] = t;
            }
        }
    }

    float ls[10], ls2[10];
    #pragma unroll
    for (int o = 0; o < 10; ++o) { ls[o] = 0.0f; ls2[o] = 0.0f; }

    float sgn = 1.0f;
    const int base = gid * KK * 10;
    #pragma unroll
    for (int e = 0; e < 9; ++e) {
        const int e2 = (e + 1 == 9) ? 0 : e + 1;
        float ax = rx[e],  ay = ry[e],  az = rz[e];
        float bx = rx[e2], by = ry[e2], bz = rz[e2];
        float cx = 0.5f * (ax + bx), cy = 0.5f * (ay + by), cz = 0.5f * (az + bz);
        float nx = ay*bz - az*by;
        float ny = az*bx - ax*bz;
        float nz = ax*by - ay*bx;
        float nnv = sqrtf(nx*nx + ny*ny + nz*nz);
        float ri = 1.0f / (nnv + 1e-6f);
        nx *= ri; ny *= ri; nz *= ri;
        if (e == 0) sgn = (nx > 0.0f) ? 1.0f : -1.0f;
        nx *= sgn; ny *= sgn; nz *= sgn;
        float pos = (nx*cx + ny*cy + nz*cz) / sqrtf(3.0f);
        float dv = ax*bx + ay*by + az*bz;
        float nA = sqrtf(ax*ax + ay*ay + az*az);
        float nB = sqrtf(bx*bx + by*by + bz*bz);
        float cv = dv / (nA * nB + 1e-8f);
        cv = fminf(1.0f, fmaxf(-1.0f, cv));
        float ang = acosf(cv);
        float f[10] = {cx, cy, cz, nx, ny, nz, pos, ang, nA, nB};
        #pragma unroll
        for (int o = 0; o < 10; ++o) {
            float h = sb[o];
            #pragma unroll
            for (int i = 0; i < 10; ++i) h = fmaf(f[i], sW[o*10+i], h);
            g_h1[base + e*10 + o] = h;
            ls[o] += h;
            ls2[o] = fmaf(h, h, ls2[o]);
        }
    }

    // block reduction of BN1 partials (4 warps)
    const int lane = tid & 31, wid = tid >> 5;
    #pragma unroll
    for (int t = 0; t < 20; ++t) {
        float v = (t < 10) ? ls[t] : ls2[t-10];
        #pragma unroll
        for (int off = 16; off > 0; off >>= 1) v += __shfl_down_sync(0xffffffffu, v, off);
        if (lane == 0) sred[wid*20 + t] = v;
    }
    __syncthreads();
    if (tid < 20) {
        float s = 0.0f;
        #pragma unroll
        for (int ww = 0; ww < 4; ++ww) s += sred[ww*20 + tid];
        g_p1[blockIdx.x * 20 + tid] = s;
    }
}

// ---------------------------------------------------------------------------
// Stats reduce: partials -> mu, rsqrt(var + eps). <<<1,160>>>
// ---------------------------------------------------------------------------
__global__ void stats_kernel(int which) {
    const float* part = which ? g_p2 : g_p1;
    const int nb = which ? NB3 : NB2;
    float* stats = which ? g_s2 : g_s1;
    __shared__ double sdd[20][8];
    __shared__ float sd[20];
    const int tid = threadIdx.x;
    if (tid < 160) {
        const int col = tid >> 3, sl = tid & 7;
        double s = 0.0;
        for (int i = sl; i < nb; i += 8) s += (double)part[i*20 + col];
        sdd[col][sl] = s;
    }
    __syncthreads();
    if (tid < 20) {
        double s = 0.0;
        #pragma unroll
        for (int i = 0; i < 8; ++i) s += sdd[tid][i];
        sd[tid] = (float)(s / (double)ROWS);
    }
    __syncthreads();
    if (tid < 10) {
        float mu = sd[tid];
        float var = fmaxf(sd[tid+10] - mu*mu, 0.0f);
        stats[tid] = mu;
        stats[10+tid] = rsqrtf(var + 1e-5f);
    }
}

// ---------------------------------------------------------------------------
// Kernel 4: BN1 + ReLU + linear2 + BN2 partial stats. <<<NB3,256>>>
// ---------------------------------------------------------------------------
__global__ void mlp2_kernel(const float* __restrict__ g1v, const float* __restrict__ be1,
                            const float* __restrict__ W2, const float* __restrict__ b2) {
    __shared__ float sW[100], sb[10], smu[10], sinv[10], sg[10], sbe[10];
    __shared__ float sred[8*20];
    const int tid = threadIdx.x;
    if (tid < 100) sW[tid] = W2[tid];
    if (tid < 10) {
        sb[tid] = b2[tid]; smu[tid] = g_s1[tid]; sinv[tid] = g_s1[10+tid];
        sg[tid] = g1v[tid]; sbe[tid] = be1[tid];
    }
    __syncthreads();
    float ls[10], ls2[10];
    #pragma unroll
    for (int o = 0; o < 10; ++o) { ls[o] = 0.0f; ls2[o] = 0.0f; }
    const int stride = gridDim.x * blockDim.x;
    for (int r = blockIdx.x * blockDim.x + tid; r < ROWS; r += stride) {
        float a[10];
        #pragma unroll
        for (int i = 0; i < 10; ++i) {
            float h = g_h1[r*10 + i];
            h = ((h - smu[i]) * sinv[i]) * sg[i] + sbe[i];
            a[i] = fmaxf(h, 0.0f);
        }
        #pragma unroll
        for (int o = 0; o < 10; ++o) {
            float h = sb[o];
            #pragma unroll
            for (int i = 0; i < 10; ++i) h = fmaf(a[i], sW[o*10+i], h);
            g_h2[r*10 + o] = h;
            ls[o] += h;
            ls2[o] = fmaf(h, h, ls2[o]);
        }
    }
    const int lane = tid & 31, wid = tid >> 5;
    #pragma unroll
    for (int t = 0; t < 20; ++t) {
        float v = (t < 10) ? ls[t] : ls2[t-10];
        #pragma unroll
        for (int off = 16; off > 0; off >>= 1) v += __shfl_down_sync(0xffffffffu, v, off);
        if (lane == 0) sred[wid*20 + t] = v;
    }
    __syncthreads();
    if (tid < 20) {
        float s = 0.0f;
        #pragma unroll
        for (int w = 0; w < 8; ++w) s += sred[w*20 + tid];
        g_p2[blockIdx.x*20 + tid] = s;
    }
}

// ---------------------------------------------------------------------------
// Kernel 6: BN2 + ReLU + max over k. <<<BB*NN/256, 256>>>
// ---------------------------------------------------------------------------
__global__ void out_kernel(const float* __restrict__ g2v, const float* __restrict__ be2,
                           float* __restrict__ out) {
    __shared__ float smu[10], sinv[10], sg[10], sbe[10];
    const int tid = threadIdx.x;
    if (tid < 10) {
        smu[tid] = g_s2[tid]; sinv[tid] = g_s2[10+tid];
        sg[tid] = g2v[tid]; sbe[tid] = be2[tid];
    }
    __syncthreads();
    const int p = blockIdx.x * blockDim.x + tid;
    float m[10];
    #pragma unroll
    for (int o = 0; o < 10; ++o) m[o] = 0.0f;  // relu outputs are >= 0
    const int base = p * KK * 10;
    #pragma unroll
    for (int e = 0; e < 9; ++e) {
        #pragma unroll
        for (int o = 0; o < 10; ++o) {
            float h = g_h2[base + e*10 + o];
            float y = fmaxf(((h - smu[o]) * sinv[o]) * sg[o] + sbe[o], 0.0f);
            m[o] = fmaxf(m[o], y);
        }
    }
    #pragma unroll
    for (int o = 0; o < 10; ++o) out[p*10 + o] = m[o];
}

// ---------------------------------------------------------------------------
extern "C" void kernel_launch(void* const* d_in, const int* in_sizes, int n_in,
                              void* d_out, int out_size) {
    (void)in_sizes; (void)n_in; (void)out_size;
    const float* x   = (const float*)d_in[0];
    const float* W1  = (const float*)d_in[1];
    const float* b1  = (const float*)d_in[2];
    const float* g1  = (const float*)d_in[3];
    const float* be1 = (const float*)d_in[4];
    const float* W2  = (const float*)d_in[5];
    const float* b2  = (const float*)d_in[6];
    const float* g2  = (const float*)d_in[7];
    const float* be2 = (const float*)d_in[8];
    float* out = (float*)d_out;

    const int smem1 = NN * 16 + 8 * QW * CAP * 8;
    cudaFuncSetAttribute(knn_kernel, cudaFuncAttributeMaxDynamicSharedMemorySize, smem1);

    dim3 grid1(NN / QB, BB);
    knn_kernel<<<grid1, 256, smem1>>>(x);
    feat_kernel<<<NB2, 128>>>(x, W1, b1);
    stats_kernel<<<1, 160>>>(0);
    mlp2_kernel<<<NB3, 256>>>(g1, be1, W2, b2);
    stats_kernel<<<1, 160>>>(1);
    out_kernel<<<(BB*NN)/256, 256>>>(g2, be2, out);
}

// round 8
// speedup vs baseline: 6.0969x; 1.4500x over previous
#include <cuda_runtime.h>
#include <math.h>
#include <float.h>

#define BB 8
#define NN 4096
#define KK 9
#define NPTS (BB*NN)        /* 32768 */
#define ROWS (NPTS*KK)      /* 294912 */
#define QB 32               /* queries per block (knn) */
#define QW 4                /* queries per warp */
#define NBF 256             /* feat partial blocks */
#define NBM 256             /* mlp partial blocks */

// Scratch (allocation-free: __device__ globals)
__device__ int   g_nbr[NPTS*KK];
__device__ float g_p1[NBF*20];
__device__ float g_p2[NBM*20];
__device__ float g_hmax[NPTS*10];
__device__ float g_hmin[NPTS*10];

__device__ __forceinline__ bool dless(float d1, int j1, float d2, int j2) {
    return d1 < d2 || (d1 == d2 && j1 < j2);
}

// Warp-distributed sorted top-10 insert (validated R4/R5/R6 fallback).
__device__ __forceinline__ void warp_insert(float nd, int nj, float& sd, int& si,
                                            const int lane) {
    const float pd = __shfl_up_sync(0xffffffffu, sd, 1);
    const int   pi = __shfl_up_sync(0xffffffffu, si, 1);
    const bool pcur  = dless(nd, nj, sd, si);
    const bool pprev = (lane > 0) && dless(nd, nj, pd, pi);
    if (pcur) { sd = pprev ? pd : nd; si = pprev ? pi : nj; }
}

// Bitonic sort of 32 values across lanes, ascending; QW interleaved for ILP.
__device__ __forceinline__ void bitonic32_val(float e[QW], const int lane) {
    #pragma unroll
    for (int k = 2; k <= 32; k <<= 1) {
        #pragma unroll
        for (int s = k >> 1; s > 0; s >>= 1) {
            const bool keepMin = (((lane & s) == 0) == ((lane & k) == 0));
            #pragma unroll
            for (int q = 0; q < QW; ++q) {
                const float oe = __shfl_xor_sync(0xffffffffu, e[q], s);
                const bool takeOther = ((oe < e[q]) == keepMin);
                e[q] = takeOther ? oe : e[q];
            }
        }
    }
}

// Bitonic sort of 32 (d,j) pairs across lanes, ascending lex (validated R6).
__device__ __forceinline__ void bitonic32_pair(float& d, int& j, const int lane) {
    #pragma unroll
    for (int k = 2; k <= 32; k <<= 1) {
        #pragma unroll
        for (int s = k >> 1; s > 0; s >>= 1) {
            const bool keepMin = (((lane & s) == 0) == ((lane & k) == 0));
            const float od = __shfl_xor_sync(0xffffffffu, d, s);
            const int   oj = __shfl_xor_sync(0xffffffffu, j, s);
            const bool takeOther = (dless(od, oj, d, j) == keepMin);
            d = takeOther ? od : d;
            j = takeOther ? oj : j;
        }
    }
}

// ---------------------------------------------------------------------------
// Kernel 1: threshold-filter kNN. Cheap shifted distance e = c.w - 2*dot
// (q2 constant cancels in comparisons); exact lex top-10 on <=32 survivors.
// grid (NN/QB, BB), block 256. smem = sx[NN] float4 + survivor j-lists.
// ---------------------------------------------------------------------------
__global__ __launch_bounds__(256, 3) void knn_kernel(const float* __restrict__ x) {
    extern __shared__ float4 sx[];                   // [NN] 64KB
    int* s_list = (int*)&sx[NN];                     // 8 warps * QW * 32 ints

    const int tid = threadIdx.x;
    const int lane = tid & 31;
    const int w = tid >> 5;
    const int b = blockIdx.y;
    const float* xb = x + (size_t)b * NN * 3;

    for (int j = tid; j < NN; j += blockDim.x) {
        float xx = xb[j*3+0], yy = xb[j*3+1], zz = xb[j*3+2];
        float ww = fmaf(zz, zz, fmaf(yy, yy, xx*xx));
        sx[j] = make_float4(xx, yy, zz, ww);
    }
    __syncthreads();

    int* list = s_list + w * (QW * 32);

    const int n0 = blockIdx.x * QB + w * QW;
    float qx[QW], qy[QW], qz[QW], q2[QW];
    #pragma unroll
    for (int q = 0; q < QW; ++q) {
        const float4 qv = sx[n0 + q];
        qx[q] = qv.x; qy[q] = qv.y; qz[q] = qv.z; q2[q] = qv.w;
    }

    // --- Pass 0: per-lane value-min of e over its 128 candidates ----------
    float e[QW];
    #pragma unroll
    for (int q = 0; q < QW; ++q) e[q] = FLT_MAX;
    for (int i = 0; i < 128; ++i) {
        const float4 c = sx[i * 32 + lane];
        #pragma unroll
        for (int q = 0; q < QW; ++q) {
            float dot = fmaf(qz[q], c.z, fmaf(qy[q], c.y, qx[q] * c.x));
            float ec = fmaf(-2.0f, dot, c.w);
            e[q] = fminf(e[q], ec);
        }
    }

    // --- threshold: 10th smallest lane-min + slack (sound: slack >> fp err)
    bitonic32_val(e, lane);
    float Tq[QW];
    #pragma unroll
    for (int q = 0; q < QW; ++q) {
        const float t = __shfl_sync(0xffffffffu, e[q], 9);
        Tq[q] = t + 1e-3f + 1e-5f * fabsf(t);
    }

    // --- Pass 1: filter + compact survivor indices (increasing j order) ---
    int cnt[QW];
    #pragma unroll
    for (int q = 0; q < QW; ++q) cnt[q] = 0;
    for (int i = 0; i < 128; ++i) {
        const int j = i * 32 + lane;
        const float4 c = sx[j];
        #pragma unroll
        for (int q = 0; q < QW; ++q) {
            float dot = fmaf(qz[q], c.z, fmaf(qy[q], c.y, qx[q] * c.x));
            float ec = fmaf(-2.0f, dot, c.w);
            const bool keep = ec <= Tq[q];
            const unsigned mask = __ballot_sync(0xffffffffu, keep);
            if (mask) {
                const int pos = cnt[q] + __popc(mask & ((1u << lane) - 1u));
                if (keep && pos < 32) list[q*32 + pos] = j;
                cnt[q] += __popc(mask);
            }
        }
    }

    // --- Pass 2: exact d (reference formula) on survivors + bitonic -------
    #pragma unroll
    for (int q = 0; q < QW; ++q) {
        int resj;
        if (cnt[q] <= 32) {
            const bool v = lane < cnt[q];
            int jj = v ? list[q*32 + lane] : 0x7fffffff;
            float dd = FLT_MAX;
            if (v) {
                const float4 c = sx[jj];
                float dot = fmaf(qz[q], c.z, fmaf(qy[q], c.y, qx[q] * c.x));
                // match reference: (x2n + x2m) - 2*dot, no fma contraction
                dd = __fsub_rn(__fadd_rn(q2[q], c.w), __fmul_rn(2.0f, dot));
            }
            bitonic32_pair(dd, jj, lane);
            resj = jj;
        } else {
            // fallback (probability ~0): exact full ballot scan (R4 method)
            float sd = FLT_MAX; int si = 0x7fffffff;
            float thr_d = FLT_MAX; int thr_j = 0x7fffffff;
            for (int j0 = 0; j0 < NN; j0 += 32) {
                const int j = j0 + lane;
                float4 c = sx[j];
                float dot = fmaf(qz[q], c.z, fmaf(qy[q], c.y, qx[q] * c.x));
                float d = __fsub_rn(__fadd_rn(q2[q], c.w), __fmul_rn(2.0f, dot));
                unsigned mask = __ballot_sync(0xffffffffu, dless(d, j, thr_d, thr_j));
                while (mask) {
                    const int src = __ffs(mask) - 1;
                    mask &= mask - 1;
                    const float nd = __shfl_sync(0xffffffffu, d, src);
                    const int   nj = j0 + src;
                    warp_insert(nd, nj, sd, si, lane);
                    thr_d = __shfl_sync(0xffffffffu, sd, 9);
                    thr_j = __shfl_sync(0xffffffffu, si, 9);
                }
            }
            resj = si;
        }
        // slots 1..9 = neighbors (slot 0 = self/nearest, dropped by reference)
        if (lane >= 1 && lane < 10) {
            g_nbr[((size_t)(b * NN) + n0 + q) * KK + (lane - 1)] = resj;
        }
    }
}

// ---------------------------------------------------------------------------
// Shared geometry: gather rel vectors for point gid, phi-sort them.
// Identical fp-op order in feat/mlp kernels.
// ---------------------------------------------------------------------------
__device__ __forceinline__ void gather_sorted_rel(const float* __restrict__ x, int gid,
                                                  float rx[9], float ry[9], float rz[9]) {
    const int bb = gid >> 12;
    const int n = gid & (NN - 1);
    const float* xb = x + (size_t)bb * NN * 3;
    const float qx = xb[n*3+0], qy = xb[n*3+1], qz = xb[n*3+2];
    float ph[9];
    #pragma unroll
    for (int e = 0; e < 9; ++e) {
        const int idx = g_nbr[(size_t)gid * KK + e];
        rx[e] = xb[idx*3+0] - qx;
        ry[e] = xb[idx*3+1] - qy;
        rz[e] = xb[idx*3+2] - qz;
        ph[e] = atan2f(ry[e], rx[e]);
    }
    // stable ascending bubble sort on phi (matches stable jnp.argsort)
    #pragma unroll
    for (int p = 0; p < 8; ++p) {
        #pragma unroll
        for (int u = 0; u < 8; ++u) {
            if (ph[u+1] < ph[u]) {
                float t;
                t = ph[u]; ph[u] = ph[u+1]; ph[u+1] = t;
                t = rx[u]; rx[u] = rx[u+1]; rx[u+1] = t;
                t = ry[u]; ry[u] = ry[u+1]; ry[u+1] = t;
                t = rz[u]; rz[u] = rz[u+1]; rz[u+1] = t;
            }
        }
    }
}

// Compute feature row e (identical fp-ops in both kernels).
__device__ __forceinline__ void feat_row(const float rx[9], const float ry[9],
                                         const float rz[9], int e, float& sgn,
                                         float f[10]) {
    const int e2 = (e + 1 == 9) ? 0 : e + 1;
    float ax = rx[e],  ay = ry[e],  az = rz[e];
    float bx = rx[e2], by = ry[e2], bz = rz[e2];
    float cx = 0.5f * (ax + bx), cy = 0.5f * (ay + by), cz = 0.5f * (az + bz);
    float nx = ay*bz - az*by;
    float ny = az*bx - ax*bz;
    float nz = ax*by - ay*bx;
    float nnv = sqrtf(nx*nx + ny*ny + nz*nz);
    float ri = 1.0f / (nnv + 1e-6f);
    nx *= ri; ny *= ri; nz *= ri;
    if (e == 0) sgn = (nx > 0.0f) ? 1.0f : -1.0f;
    nx *= sgn; ny *= sgn; nz *= sgn;
    float pos = (nx*cx + ny*cy + nz*cz) / sqrtf(3.0f);
    float dv = ax*bx + ay*by + az*bz;
    float nA = sqrtf(ax*ax + ay*ay + az*az);
    float nB = sqrtf(bx*bx + by*by + bz*bz);
    float cv = dv / (nA * nB + 1e-8f);
    cv = fminf(1.0f, fmaxf(-1.0f, cv));
    float ang = acosf(cv);
    f[0]=cx; f[1]=cy; f[2]=cz; f[3]=nx; f[4]=ny; f[5]=nz;
    f[6]=pos; f[7]=ang; f[8]=nA; f[9]=nB;
}

// ---------------------------------------------------------------------------
// Kernel 2: features + linear1 -> BN1 partial stats only (no h1 stored).
// <<<NBF,128>>>, thread per point.
// ---------------------------------------------------------------------------
__global__ __launch_bounds__(128) void feat_kernel(const float* __restrict__ x,
                                                   const float* __restrict__ W1,
                                                   const float* __restrict__ b1) {
    __shared__ float sW[100], sb[10];
    __shared__ float sred[4*20];
    const int tid = threadIdx.x;
    if (tid < 100) sW[tid] = W1[tid];
    if (tid < 10)  sb[tid] = b1[tid];
    __syncthreads();

    const int gid = blockIdx.x * blockDim.x + tid;
    float rx[9], ry[9], rz[9];
    gather_sorted_rel(x, gid, rx, ry, rz);

    float ls[10], ls2[10];
    #pragma unroll
    for (int o = 0; o < 10; ++o) { ls[o] = 0.0f; ls2[o] = 0.0f; }
    float sgn = 1.0f;
    #pragma unroll
    for (int e = 0; e < 9; ++e) {
        float f[10];
        feat_row(rx, ry, rz, e, sgn, f);
        #pragma unroll
        for (int o = 0; o < 10; ++o) {
            float h = sb[o];
            #pragma unroll
            for (int i = 0; i < 10; ++i) h = fmaf(f[i], sW[o*10+i], h);
            ls[o] += h;
            ls2[o] = fmaf(h, h, ls2[o]);
        }
    }

    const int lane = tid & 31, wid = tid >> 5;
    #pragma unroll
    for (int t = 0; t < 20; ++t) {
        float v = (t < 10) ? ls[t] : ls2[t-10];
        #pragma unroll
        for (int off = 16; off > 0; off >>= 1) v += __shfl_down_sync(0xffffffffu, v, off);
        if (lane == 0) sred[wid*20 + t] = v;
    }
    __syncthreads();
    if (tid < 20) {
        float s = 0.0f;
        #pragma unroll
        for (int ww = 0; ww < 4; ++ww) s += sred[ww*20 + tid];
        g_p1[blockIdx.x * 20 + tid] = s;
    }
}

// Inline stats: reduce part[nb*20] -> sstat[0..9]=mu, [10..19]=rsqrt(var+eps).
// 128-thread block; deterministic fixed-order double reduction.
__device__ __forceinline__ void block_stats(const float* part, int nb, float* sstat,
                                            double sdd[20][4], int tid) {
    if (tid < 80) {
        const int col = tid >> 2, sl = tid & 3;
        double s = 0.0;
        for (int i = sl; i < nb; i += 4) s += (double)part[i*20 + col];
        sdd[col][sl] = s;
    }
    __syncthreads();
    if (tid < 20) {
        double s = 0.0;
        #pragma unroll
        for (int i = 0; i < 4; ++i) s += sdd[tid][i];
        sstat[tid] = (float)(s / (double)ROWS);
    }
    __syncthreads();
    if (tid < 10) {
        const float mu = sstat[tid];
        const float var = fmaxf(sstat[tid+10] - mu*mu, 0.0f);
        sstat[10+tid] = rsqrtf(var + 1e-5f);
    }
    __syncthreads();
}

// ---------------------------------------------------------------------------
// Kernel 3: fused BN1+ReLU+linear2; writes per-point max/min of h2 over k
// + BN2 partials. <<<NBM,128>>>, thread per point. Inline BN1 stats.
// ---------------------------------------------------------------------------
__global__ __launch_bounds__(128) void mlp_kernel(const float* __restrict__ x,
                                                  const float* __restrict__ W1,
                                                  const float* __restrict__ b1,
                                                  const float* __restrict__ g1v,
                                                  const float* __restrict__ be1,
                                                  const float* __restrict__ W2,
                                                  const float* __restrict__ b2) {
    __shared__ double sdd[20][4];
    __shared__ float sstat[20];
    __shared__ float sW1[100], sb1[10], sW2[100], sb2[10], sg1[10], sbe1[10];
    __shared__ float sred[4*20];
    const int tid = threadIdx.x;
    if (tid < 100) { sW1[tid] = W1[tid]; sW2[tid] = W2[tid]; }
    if (tid < 10) { sb1[tid] = b1[tid]; sb2[tid] = b2[tid];
                    sg1[tid] = g1v[tid]; sbe1[tid] = be1[tid]; }
    block_stats(g_p1, NBF, sstat, sdd, tid);

    const int gid = blockIdx.x * blockDim.x + tid;
    float rx[9], ry[9], rz[9];
    gather_sorted_rel(x, gid, rx, ry, rz);

    float ls[10], ls2[10], hmax[10], hmin[10];
    #pragma unroll
    for (int o = 0; o < 10; ++o) {
        ls[o] = 0.0f; ls2[o] = 0.0f; hmax[o] = -FLT_MAX; hmin[o] = FLT_MAX;
    }
    float sgn = 1.0f;
    #pragma unroll
    for (int e = 0; e < 9; ++e) {
        float f[10];
        feat_row(rx, ry, rz, e, sgn, f);
        float a[10];
        #pragma unroll
        for (int o = 0; o < 10; ++o) {
            float h = sb1[o];
            #pragma unroll
            for (int i = 0; i < 10; ++i) h = fmaf(f[i], sW1[o*10+i], h);
            h = ((h - sstat[o]) * sstat[10+o]) * sg1[o] + sbe1[o];
            a[o] = fmaxf(h, 0.0f);
        }
        #pragma unroll
        for (int o = 0; o < 10; ++o) {
            float h = sb2[o];
            #pragma unroll
            for (int i = 0; i < 10; ++i) h = fmaf(a[i], sW2[o*10+i], h);
            ls[o] += h;
            ls2[o] = fmaf(h, h, ls2[o]);
            hmax[o] = fmaxf(hmax[o], h);
            hmin[o] = fminf(hmin[o], h);
        }
    }
    #pragma unroll
    for (int o = 0; o < 10; ++o) {
        g_hmax[gid*10 + o] = hmax[o];
        g_hmin[gid*10 + o] = hmin[o];
    }

    const int lane = tid & 31, wid = tid >> 5;
    #pragma unroll
    for (int t = 0; t < 20; ++t) {
        float v = (t < 10) ? ls[t] : ls2[t-10];
        #pragma unroll
        for (int off = 16; off > 0; off >>= 1) v += __shfl_down_sync(0xffffffffu, v, off);
        if (lane == 0) sred[wid*20 + t] = v;
    }
    __syncthreads();
    if (tid < 20) {
        float s = 0.0f;
        #pragma unroll
        for (int ww = 0; ww < 4; ++ww) s += sred[ww*20 + tid];
        g_p2[blockIdx.x * 20 + tid] = s;
    }
}

// ---------------------------------------------------------------------------
// Kernel 4: inline BN2 stats + monotone max trick + ReLU. <<<NPTS/128,128>>>
// BN2 affine is monotone in h with direction sign(g2) (inv>0), and relu+max
// commute with monotone maps: max_k relu(aff(h)) = relu(aff(max_k h)) (g>=0)
// or relu(aff(min_k h)) (g<0). Values bit-identical to per-element eval.
// ---------------------------------------------------------------------------
__global__ __launch_bounds__(128) void out_kernel(const float* __restrict__ g2v,
                                                  const float* __restrict__ be2,
                                                  float* __restrict__ out) {
    __shared__ double sdd[20][4];
    __shared__ float sstat[20];
    __shared__ float sg[10], sbe[10];
    const int tid = threadIdx.x;
    if (tid < 10) { sg[tid] = g2v[tid]; sbe[tid] = be2[tid]; }
    block_stats(g_p2, NBM, sstat, sdd, tid);

    const int gid = blockIdx.x * blockDim.x + tid;
    #pragma unroll
    for (int o = 0; o < 10; ++o) {
        const float g = sg[o];
        const float h = (g >= 0.0f) ? g_hmax[gid*10 + o] : g_hmin[gid*10 + o];
        const float y = fmaxf(((h - sstat[o]) * sstat[10+o]) * g + sbe[o], 0.0f);
        out[gid*10 + o] = y;
    }
}

// ---------------------------------------------------------------------------
extern "C" void kernel_launch(void* const* d_in, const int* in_sizes, int n_in,
                              void* d_out, int out_size) {
    (void)in_sizes; (void)n_in; (void)out_size;
    const float* x   = (const float*)d_in[0];
    const float* W1  = (const float*)d_in[1];
    const float* b1  = (const float*)d_in[2];
    const float* g1  = (const float*)d_in[3];
    const float* be1 = (const float*)d_in[4];
    const float* W2  = (const float*)d_in[5];
    const float* b2  = (const float*)d_in[6];
    const float* g2  = (const float*)d_in[7];
    const float* be2 = (const float*)d_in[8];
    float* out = (float*)d_out;

    const int smem1 = NN * 16 + 8 * QW * 32 * 4;
    cudaFuncSetAttribute(knn_kernel, cudaFuncAttributeMaxDynamicSharedMemorySize, smem1);

    dim3 grid1(NN / QB, BB);
    knn_kernel<<<grid1, 256, smem1>>>(x);
    feat_kernel<<<NBF, 128>>>(x, W1, b1);
    mlp_kernel<<<NBM, 128>>>(x, W1, b1, g1, be1, W2, b2);
    out_kernel<<<NPTS/128, 128>>>(g2, be2, out);
}